// round 9
// baseline (speedup 1.0000x reference)
#include <cuda_runtime.h>
#include <cstdint>
#include <math.h>

// Inputs: a [4096,128] f32, p [4096,128] f32, n [4096,128] f32. Output: 1 f32.

#define B_SIZE 4096
#define DIM    128
#define NTOT   12288
#define NTILES 96
#define TPB    256
#define MARGIN 0.4f
#define ALPHA  0.01f

#define QSCALE  23.0f
#define SCALE2  (2.0f / (QSCALE * QSCALE))

// ---- smem layout (bytes) ----
#define OFF_SQJ(b)  ((b) * 512)                 // fp32 sqj per buffer
#define OFF_COLMIN  1024
#define OFF_A       2048                        // 128x128 s8 = 16KB
#define OFF_B(b)    (OFF_A + 16384 + (b) * 16384)
#define SMEM_TOTAL  (OFF_A + 16384 + 2 * 16384) // 51200

// ---- device scratch ----
__device__ float         g_sq[NTOT];
__device__ unsigned int  g_rowmin[NTOT];
__device__ float         g_posmax[NTOT];
__device__ float         g_regpart[NTOT];
__device__ uint32_t      g_q[NTOT * 32];        // 4 int8 per uint32, 32/row

// ---- helpers ----
__device__ __forceinline__ uint32_t smem_u32(const void* p) {
    uint32_t a;
    asm("{ .reg .u64 t; cvta.to.shared.u64 t, %1; cvt.u32.u64 %0, t; }"
        : "=r"(a) : "l"(p));
    return a;
}
__device__ __forceinline__ void cp16(uint32_t dst, const void* src) {
    asm volatile("cp.async.cg.shared.global [%0], [%1], 16;"
                 :: "r"(dst), "l"(src));
}
#define CP_COMMIT() asm volatile("cp.async.commit_group;" ::: "memory")
#define CP_WAIT(n)  asm volatile("cp.async.wait_group %0;" :: "n"(n) : "memory")

__device__ __forceinline__ void ldsm4(uint32_t* r, uint32_t addr) {
    asm volatile("ldmatrix.sync.aligned.m8n8.x4.shared.b16 {%0,%1,%2,%3}, [%4];"
                 : "=r"(r[0]), "=r"(r[1]), "=r"(r[2]), "=r"(r[3]) : "r"(addr));
}
// int8 MMA: m16n8k32, s8 x s8 -> s32
__device__ __forceinline__ void imma16832(int* d, const uint32_t* a,
                                          uint32_t b0, uint32_t b1) {
    asm volatile("mma.sync.aligned.m16n8k32.row.col.s32.s8.s8.s32 "
                 "{%0,%1,%2,%3}, {%4,%5,%6,%7}, {%8,%9}, {%0,%1,%2,%3};"
                 : "+r"(d[0]), "+r"(d[1]), "+r"(d[2]), "+r"(d[3])
                 : "r"(a[0]), "r"(a[1]), "r"(a[2]), "r"(a[3]),
                   "r"(b0), "r"(b1));
}

// ---------------------------------------------------------------------------
// prep: one warp per column c; loads a_c/p_c/n_c once; emits fp32 stats +
// int8 quantization (x -> clamp(round(x*QSCALE), ±127)).
// ---------------------------------------------------------------------------
__global__ void __launch_bounds__(256) prep_kernel(const float* __restrict__ a,
                                                   const float* __restrict__ p,
                                                   const float* __restrict__ n) {
    int c    = (blockIdx.x * 256 + threadIdx.x) >> 5;   // 0..4095
    int lane = threadIdx.x & 31;

    float4 xa = reinterpret_cast<const float4*>(a + (size_t)c * DIM)[lane];
    float4 xp = reinterpret_cast<const float4*>(p + (size_t)c * DIM)[lane];
    float4 xn = reinterpret_cast<const float4*>(n + (size_t)c * DIM)[lane];

    float as[4] = {xa.x, xa.y, xa.z, xa.w};
    float ps[4] = {xp.x, xp.y, xp.z, xp.w};
    float ns[4] = {xn.x, xn.y, xn.z, xn.w};

    float sqa = 0.f, sqp = 0.f, sqn = 0.f;
    float ra = 0.f, rp = 0.f, rn = 0.f;
    float eap = 0.f, ean = 0.f, epn = 0.f;
    #pragma unroll
    for (int i = 0; i < 4; i++) {
        sqa += as[i] * as[i];  sqp += ps[i] * ps[i];  sqn += ns[i] * ns[i];
        float ta = fabsf(as[i]) - 1.f; ra += ta * ta;
        float tp = fabsf(ps[i]) - 1.f; rp += tp * tp;
        float tn = fabsf(ns[i]) - 1.f; rn += tn * tn;
        float d1 = as[i] - ps[i]; eap += d1 * d1;
        float d2 = as[i] - ns[i]; ean += d2 * d2;
        float d3 = ps[i] - ns[i]; epn += d3 * d3;
    }
    #pragma unroll
    for (int ofs = 16; ofs; ofs >>= 1) {
        sqa += __shfl_xor_sync(0xffffffffu, sqa, ofs);
        sqp += __shfl_xor_sync(0xffffffffu, sqp, ofs);
        sqn += __shfl_xor_sync(0xffffffffu, sqn, ofs);
        ra  += __shfl_xor_sync(0xffffffffu, ra,  ofs);
        rp  += __shfl_xor_sync(0xffffffffu, rp,  ofs);
        rn  += __shfl_xor_sync(0xffffffffu, rn,  ofs);
        eap += __shfl_xor_sync(0xffffffffu, eap, ofs);
        ean += __shfl_xor_sync(0xffffffffu, ean, ofs);
        epn += __shfl_xor_sync(0xffffffffu, epn, ofs);
    }
    if (lane == 0) {
        g_sq[c]              = sqa;
        g_sq[c + B_SIZE]     = sqp;
        g_sq[c + 2 * B_SIZE] = sqn;
        g_regpart[c]              = ra;
        g_regpart[c + B_SIZE]     = rp;
        g_regpart[c + 2 * B_SIZE] = rn;
        g_posmax[c]               = fmaxf(eap, ean);
        g_posmax[c + B_SIZE]      = fmaxf(eap, epn);
        g_posmax[c + 2 * B_SIZE]  = fmaxf(ean, epn);
        g_rowmin[c]               = 0x7f800000u;
        g_rowmin[c + B_SIZE]      = 0x7f800000u;
        g_rowmin[c + 2 * B_SIZE]  = 0x7f800000u;
    }

    #pragma unroll
    for (int seg = 0; seg < 3; seg++) {
        const float* s = (seg == 0) ? as : (seg == 1) ? ps : ns;
        uint32_t packed = 0;
        #pragma unroll
        for (int i = 0; i < 4; i++) {
            float q = rintf(s[i] * QSCALE);
            q = fminf(fmaxf(q, -127.f), 127.f);
            int qi = (int)q;
            packed |= ((uint32_t)(qi & 0xff)) << (8 * i);
        }
        g_q[(c + seg * B_SIZE) * 32 + lane] = packed;
    }
}

// ---------------------------------------------------------------------------
// prefetch one 128x128 int8 tile (16KB) global -> swizzled smem.
// row m at off + m*128; 16B chunk c stored at chunk (c ^ (m&7)).
// ---------------------------------------------------------------------------
__device__ __forceinline__ void prefetch_tile(int rowbase, uint32_t sm_off,
                                              uint32_t sb, int tid) {
    const uint4* src = reinterpret_cast<const uint4*>(g_q) + (size_t)rowbase * 8;
    #pragma unroll
    for (int i = 0; i < 4; i++) {
        int ch = tid + i * 256;              // 0..1023
        int m = ch >> 3, c = ch & 7;
        uint32_t dst = sb + sm_off + ((uint32_t)m << 7) + ((uint32_t)(c ^ (m & 7)) << 4);
        cp16(dst, src + ch);
    }
}
__device__ __forceinline__ void stage_sq(uint32_t sb, int buf, int jt, int tid) {
    if (tid < 32) cp16(sb + OFF_SQJ(buf) + tid * 16, g_sq + jt * 128 + tid * 4);
}

// ---------------------------------------------------------------------------
// tile kernel: symmetric cyclic coverage, int8 IMMA m16n8k32.
// ---------------------------------------------------------------------------
__global__ void __launch_bounds__(TPB, 2) tile_kernel() {
    extern __shared__ char smem[];
    uint32_t sb = smem_u32(smem);
    const int tid  = threadIdx.x;
    const int wid  = tid >> 5;
    const int lane = tid & 31;

    const int bi   = blockIdx.x / 3;
    const int grp  = blockIdx.x % 3;
    const int d0   = grp * 16;
    const int ntl  = 16 + ((grp == 2 && bi < 48) ? 1 : 0);
    const int rowbase = bi * 128;

    // warp layout: 2 warps in M (64 rows) x 4 warps in N (32 cols)
    const int wy  = wid & 1,  wx = wid >> 1;
    const int m0w = wy * 64,  n0w = wx * 32;

    const int bj0 = (bi + d0) % NTILES;
    prefetch_tile(rowbase, OFF_A, sb, tid);
    prefetch_tile(bj0 * 128, OFF_B(0), sb, tid);
    stage_sq(sb, 0, bj0, tid);
    CP_COMMIT();

    unsigned int* colmin = reinterpret_cast<unsigned int*>(smem + OFF_COLMIN);
    if (tid < 128) colmin[tid] = 0x7f800000u;

    float sqi[4][2];
    float rmin[4][2];
    #pragma unroll
    for (int mt = 0; mt < 4; mt++)
        #pragma unroll
        for (int h = 0; h < 2; h++) {
            int r = m0w + mt * 16 + (lane >> 2) + h * 8;
            sqi[mt][h]  = g_sq[rowbase + r];
            rmin[mt][h] = __int_as_float(0x7f800000);
        }

    const int a_rbit = (lane >> 3) & 1;   // +8 rows for matrices 1,3
    const int a_cbit = (lane >> 4) & 1;   // +16 bytes (k) for matrices 2,3
    const int b_rbit = (lane >> 4) & 1;   // +8 n-rows for matrices 2,3
    const int b_cbit = (lane >> 3) & 1;   // +16 bytes (k) for matrices 1,3
    const int l7 = lane & 7;

    for (int t = 0; t < ntl; t++) {
        const int b  = t & 1, nb = b ^ 1;
        const int jt = (bi + d0 + t) % NTILES;

        if (t + 1 < ntl) {
            const int jn = (bi + d0 + t + 1) % NTILES;
            prefetch_tile(jn * 128, OFF_B(nb), sb, tid);
            stage_sq(sb, nb, jn, tid);
            CP_COMMIT();
            CP_WAIT(1);
        } else {
            CP_WAIT(0);
        }
        __syncthreads();

        // ---- IMMA: K=128 int8, 4 k-steps of 32 ----
        int acc[4][4][4];
        #pragma unroll
        for (int mt = 0; mt < 4; mt++)
            #pragma unroll
            for (int nt = 0; nt < 4; nt++)
                #pragma unroll
                for (int k = 0; k < 4; k++) acc[mt][nt][k] = 0;

        const uint32_t Ab = sb + OFF_A, Bb = sb + OFF_B(b);

        #pragma unroll
        for (int ks = 0; ks < 4; ks++) {
            const int c0 = ks * 2;            // 16B chunks; 32B per k-step
            uint32_t af[4][4], bf[2][4];
            #pragma unroll
            for (int mt = 0; mt < 4; mt++) {
                int row = m0w + mt * 16 + l7 + a_rbit * 8;
                ldsm4(af[mt], Ab + ((uint32_t)row << 7) +
                              ((uint32_t)((c0 + a_cbit) ^ (row & 7)) << 4));
            }
            #pragma unroll
            for (int bt = 0; bt < 2; bt++) {
                int row = n0w + bt * 16 + l7 + b_rbit * 8;
                ldsm4(bf[bt], Bb + ((uint32_t)row << 7) +
                              ((uint32_t)((c0 + b_cbit) ^ (row & 7)) << 4));
            }
            #pragma unroll
            for (int mt = 0; mt < 4; mt++)
                #pragma unroll
                for (int nt = 0; nt < 4; nt++)
                    imma16832(acc[mt][nt], af[mt],
                              bf[nt >> 1][(nt & 1) * 2],
                              bf[nt >> 1][(nt & 1) * 2 + 1]);
        }

        // ---- epilogue: d^2 = sqi + sqj - SCALE2*acc, mask, mins ----
        const float* sqj = reinterpret_cast<const float*>(smem + OFF_SQJ(b));
        const bool diag = ((bi & 31) == (jt & 31));
        const float FINF = __int_as_float(0x7f800000);

        float cmin[4][2];
        #pragma unroll
        for (int nt = 0; nt < 4; nt++) { cmin[nt][0] = FINF; cmin[nt][1] = FINF; }

        #pragma unroll
        for (int mt = 0; mt < 4; mt++) {
            const int r0 = m0w + mt * 16 + (lane >> 2);
            const int r1 = r0 + 8;
            #pragma unroll
            for (int nt = 0; nt < 4; nt++) {
                const int c0i = n0w + nt * 8 + (lane & 3) * 2;
                float2 sj = *reinterpret_cast<const float2*>(&sqj[c0i]);
                float s0x = sqi[mt][0] + sj.x, s0y = sqi[mt][0] + sj.y;
                float s1x = sqi[mt][1] + sj.x, s1y = sqi[mt][1] + sj.y;
                float d00 = fmaf(__int2float_rn(acc[mt][nt][0]), -SCALE2, s0x);
                float d01 = fmaf(__int2float_rn(acc[mt][nt][1]), -SCALE2, s0y);
                float d10 = fmaf(__int2float_rn(acc[mt][nt][2]), -SCALE2, s1x);
                float d11 = fmaf(__int2float_rn(acc[mt][nt][3]), -SCALE2, s1y);
                if (diag) {
                    if (r0 == c0i)     d00 = FINF;
                    if (r0 == c0i + 1) d01 = FINF;
                    if (r1 == c0i)     d10 = FINF;
                    if (r1 == c0i + 1) d11 = FINF;
                }
                rmin[mt][0] = fminf(rmin[mt][0], fminf(d00, d01));
                rmin[mt][1] = fminf(rmin[mt][1], fminf(d10, d11));
                cmin[nt][0] = fminf(cmin[nt][0], fminf(d00, d10));
                cmin[nt][1] = fminf(cmin[nt][1], fminf(d01, d11));
            }
        }

        // col reduce across row-groups (lane>>2) then smem colmin
        #pragma unroll
        for (int nt = 0; nt < 4; nt++)
            #pragma unroll
            for (int h = 0; h < 2; h++) {
                float v = cmin[nt][h];
                v = fminf(v, __shfl_xor_sync(0xffffffffu, v, 4));
                v = fminf(v, __shfl_xor_sync(0xffffffffu, v, 8));
                v = fminf(v, __shfl_xor_sync(0xffffffffu, v, 16));
                cmin[nt][h] = v;
            }
        if (lane < 4) {
            #pragma unroll
            for (int nt = 0; nt < 4; nt++) {
                int c = n0w + nt * 8 + lane * 2;
                atomicMin(&colmin[c],     __float_as_uint(fmaxf(cmin[nt][0], 0.f)));
                atomicMin(&colmin[c + 1], __float_as_uint(fmaxf(cmin[nt][1], 0.f)));
            }
        }
        __syncthreads();

        if (tid < 128) {
            atomicMin(&g_rowmin[jt * 128 + tid], colmin[tid]);
            colmin[tid] = 0x7f800000u;
        }
    }

    // ---- final row-min: reduce column-lanes, global atomic ----
    #pragma unroll
    for (int mt = 0; mt < 4; mt++)
        #pragma unroll
        for (int h = 0; h < 2; h++) {
            float v = rmin[mt][h];
            v = fminf(v, __shfl_xor_sync(0xffffffffu, v, 1));
            v = fminf(v, __shfl_xor_sync(0xffffffffu, v, 2));
            if ((lane & 3) == 0) {
                int r = m0w + mt * 16 + (lane >> 2) + h * 8;
                atomicMin(&g_rowmin[rowbase + r], __float_as_uint(fmaxf(v, 0.f)));
            }
        }
}

// ---------------------------------------------------------------------------
__global__ void finalize_kernel(float* __restrict__ out) {
    __shared__ float sl[1024];
    __shared__ float sr[1024];
    int t = threadIdx.x;
    float ls = 0.0f, rs = 0.0f;
    for (int i = t; i < NTOT; i += 1024) {
        float pm = g_posmax[i];
        float nm = __uint_as_float(g_rowmin[i]);
        float pd = (pm > 0.0f) ? sqrtf(pm) : 0.0f;
        float nd = (nm > 0.0f) ? sqrtf(nm) : 0.0f;
        ls += fmaxf(pd - nd + MARGIN, 0.0f);
        rs += g_regpart[i];
    }
    sl[t] = ls; sr[t] = rs;
    __syncthreads();
    #pragma unroll
    for (int s = 512; s; s >>= 1) {
        if (t < s) { sl[t] += sl[t + s]; sr[t] += sr[t + s]; }
        __syncthreads();
    }
    if (t == 0)
        out[0] = sl[0] / (float)NTOT + ALPHA * (sr[0] / (float)(NTOT * DIM));
}

// ---------------------------------------------------------------------------
extern "C" void kernel_launch(void* const* d_in, const int* in_sizes, int n_in,
                              void* d_out, int out_size) {
    const float* a = (const float*)d_in[0];
    const float* p = (const float*)d_in[1];
    const float* n = (const float*)d_in[2];
    float* out = (float*)d_out;

    cudaFuncSetAttribute(tile_kernel,
                         cudaFuncAttributeMaxDynamicSharedMemorySize, SMEM_TOTAL);

    prep_kernel<<<B_SIZE / 8, 256>>>(a, p, n);
    tile_kernel<<<NTILES * 3, TPB, SMEM_TOTAL>>>();
    finalize_kernel<<<1, 1024>>>(out);
}

// round 10
// speedup vs baseline: 1.8783x; 1.8783x over previous
#include <cuda_runtime.h>
#include <cuda_fp16.h>
#include <cstdint>
#include <math.h>

// Inputs: a [4096,128] f32, p [4096,128] f32, n [4096,128] f32. Output: 1 f32.

#define B_SIZE 4096
#define DIM    128
#define NTOT   12288
#define NTILES 96
#define TPB    256
#define GRID   (NTILES * 3)       // 288 CTAs, all resident (2/SM x 148 SMs)
#define MARGIN 0.4f
#define ALPHA  0.01f

// ---- smem layout (bytes) ----
#define OFF_SQJ(b)  ((b) * 512)          // fp32 sqj, per buffer
#define OFF_COLMIN  1024
#define OFF_SQJH(b) (1536 + (b) * 256)   // fp16 sqj, per buffer
#define OFF_A       2048
#define OFF_B(b)    (OFF_A + 32768 + (b) * 32768)
#define SMEM_TOTAL  (OFF_A + 32768 + 2 * 32768)   // 100352

// ---- device scratch ----
__device__ float         g_sq[NTOT];
__device__ __half        g_sqh[NTOT];
__device__ unsigned int  g_rowmin[NTOT];
__device__ float         g_posmax[NTOT];
__device__ float         g_regpart[NTOT];
__device__ __half        g_h[NTOT * DIM];
__device__ unsigned int  g_bar1 = 0;
__device__ unsigned int  g_bar2 = 0;

// ---- helpers ----
__device__ __forceinline__ uint32_t smem_u32(const void* p) {
    uint32_t a;
    asm("{ .reg .u64 t; cvta.to.shared.u64 t, %1; cvt.u32.u64 %0, t; }"
        : "=r"(a) : "l"(p));
    return a;
}
__device__ __forceinline__ void cp16(uint32_t dst, const void* src) {
    asm volatile("cp.async.cg.shared.global [%0], [%1], 16;"
                 :: "r"(dst), "l"(src));
}
#define CP_COMMIT() asm volatile("cp.async.commit_group;" ::: "memory")
#define CP_WAIT(n)  asm volatile("cp.async.wait_group %0;" :: "n"(n) : "memory")

__device__ __forceinline__ void ldsm4(uint32_t* r, uint32_t addr) {
    asm volatile("ldmatrix.sync.aligned.m8n8.x4.shared.b16 {%0,%1,%2,%3}, [%4];"
                 : "=r"(r[0]), "=r"(r[1]), "=r"(r[2]), "=r"(r[3]) : "r"(addr));
}
__device__ __forceinline__ void mma16816h(uint32_t* d, const uint32_t* a,
                                          uint32_t b0, uint32_t b1) {
    asm volatile("mma.sync.aligned.m16n8k16.row.col.f16.f16.f16.f16 "
                 "{%0,%1}, {%2,%3,%4,%5}, {%6,%7}, {%0,%1};"
                 : "+r"(d[0]), "+r"(d[1])
                 : "r"(a[0]), "r"(a[1]), "r"(a[2]), "r"(a[3]),
                   "r"(b0), "r"(b1));
}
__device__ __forceinline__ __half2 shfl_hmin2(__half2 v, int ofs) {
    uint32_t u = __shfl_xor_sync(0xffffffffu,
                                 *reinterpret_cast<uint32_t*>(&v), ofs);
    return __hmin2(v, *reinterpret_cast<__half2*>(&u));
}

__device__ __forceinline__ void prefetch_tile(const __half* __restrict__ g,
                                              int rowbase, uint32_t sm_off,
                                              uint32_t sb, int tid) {
    const uint4* src = reinterpret_cast<const uint4*>(g) + (size_t)rowbase * 16;
    #pragma unroll
    for (int i = 0; i < 8; i++) {
        int ch = tid + i * 256;
        int m = ch >> 4, c = ch & 15;
        uint32_t dst = sb + sm_off + ((uint32_t)m << 8) + ((uint32_t)(c ^ (m & 7)) << 4);
        cp16(dst, src + ch);
    }
}
__device__ __forceinline__ void stage_sq(uint32_t sb, int buf, int jt, int tid) {
    if (tid < 32) cp16(sb + OFF_SQJ(buf) + tid * 16, g_sq + jt * 128 + tid * 4);
    else if (tid < 48)
        cp16(sb + OFF_SQJH(buf) + (tid - 32) * 16, g_sqh + jt * 128 + (tid - 32) * 8);
}

// ---------------------------------------------------------------------------
// fused kernel: phase 1 prep -> grid barrier -> phase 2 tiles -> phase 3 final
// ---------------------------------------------------------------------------
__global__ void __launch_bounds__(TPB, 2) fused_kernel(const float* __restrict__ a,
                                                       const float* __restrict__ p,
                                                       const float* __restrict__ n,
                                                       float* __restrict__ out) {
    extern __shared__ char smem[];
    uint32_t sb = smem_u32(smem);
    const int tid  = threadIdx.x;
    const int wid  = tid >> 5;
    const int lane = tid & 31;

    // ================= phase 1: prep (warp per column, strided) =============
    for (int c = blockIdx.x * 8 + wid; c < B_SIZE; c += GRID * 8) {
        float4 xa = reinterpret_cast<const float4*>(a + (size_t)c * DIM)[lane];
        float4 xp = reinterpret_cast<const float4*>(p + (size_t)c * DIM)[lane];
        float4 xn = reinterpret_cast<const float4*>(n + (size_t)c * DIM)[lane];

        float as[4] = {xa.x, xa.y, xa.z, xa.w};
        float ps[4] = {xp.x, xp.y, xp.z, xp.w};
        float ns[4] = {xn.x, xn.y, xn.z, xn.w};

        float sqa = 0.f, sqp = 0.f, sqn = 0.f;
        float ra = 0.f, rp = 0.f, rn = 0.f;
        float eap = 0.f, ean = 0.f, epn = 0.f;
        #pragma unroll
        for (int i = 0; i < 4; i++) {
            sqa += as[i] * as[i];  sqp += ps[i] * ps[i];  sqn += ns[i] * ns[i];
            float ta = fabsf(as[i]) - 1.f; ra += ta * ta;
            float tp = fabsf(ps[i]) - 1.f; rp += tp * tp;
            float tn = fabsf(ns[i]) - 1.f; rn += tn * tn;
            float d1 = as[i] - ps[i]; eap += d1 * d1;
            float d2 = as[i] - ns[i]; ean += d2 * d2;
            float d3 = ps[i] - ns[i]; epn += d3 * d3;
        }
        #pragma unroll
        for (int ofs = 16; ofs; ofs >>= 1) {
            sqa += __shfl_xor_sync(0xffffffffu, sqa, ofs);
            sqp += __shfl_xor_sync(0xffffffffu, sqp, ofs);
            sqn += __shfl_xor_sync(0xffffffffu, sqn, ofs);
            ra  += __shfl_xor_sync(0xffffffffu, ra,  ofs);
            rp  += __shfl_xor_sync(0xffffffffu, rp,  ofs);
            rn  += __shfl_xor_sync(0xffffffffu, rn,  ofs);
            eap += __shfl_xor_sync(0xffffffffu, eap, ofs);
            ean += __shfl_xor_sync(0xffffffffu, ean, ofs);
            epn += __shfl_xor_sync(0xffffffffu, epn, ofs);
        }
        if (lane == 0) {
            g_sq[c]              = sqa;
            g_sq[c + B_SIZE]     = sqp;
            g_sq[c + 2 * B_SIZE] = sqn;
            g_sqh[c]              = __float2half_rn(sqa);
            g_sqh[c + B_SIZE]     = __float2half_rn(sqp);
            g_sqh[c + 2 * B_SIZE] = __float2half_rn(sqn);
            g_regpart[c]              = ra;
            g_regpart[c + B_SIZE]     = rp;
            g_regpart[c + 2 * B_SIZE] = rn;
            g_posmax[c]               = fmaxf(eap, ean);
            g_posmax[c + B_SIZE]      = fmaxf(eap, epn);
            g_posmax[c + 2 * B_SIZE]  = fmaxf(ean, epn);
            g_rowmin[c]               = 0x7f800000u;
            g_rowmin[c + B_SIZE]      = 0x7f800000u;
            g_rowmin[c + 2 * B_SIZE]  = 0x7f800000u;
        }
        #pragma unroll
        for (int seg = 0; seg < 3; seg++) {
            const float* s = (seg == 0) ? as : (seg == 1) ? ps : ns;
            unsigned h0 = 0, h1 = 0;
            #pragma unroll
            for (int i = 0; i < 4; i++) {
                unsigned hb = __half_as_ushort(__float2half_rn(s[i]));
                if (i < 2) h0 |= hb << (16 * i);
                else       h1 |= hb << (16 * (i - 2));
            }
            reinterpret_cast<uint2*>(g_h)[(c + seg * B_SIZE) * 32 + lane] =
                make_uint2(h0, h1);
        }
    }

    // ---- grid-wide barrier (all 288 CTAs resident -> no deadlock) ----
    __syncthreads();
    if (tid == 0) {
        __threadfence();
        atomicAdd(&g_bar1, 1u);
        volatile unsigned int* vb = &g_bar1;
        while (*vb < (unsigned)GRID) __nanosleep(64);
    }
    __syncthreads();
    __threadfence();

    // ================= phase 2: tile loop (round-7 structure) ================
    const int bi   = blockIdx.x / 3;
    const int grp  = blockIdx.x % 3;
    const int d0   = grp * 16;
    const int ntl  = 16 + ((grp == 2 && bi < 48) ? 1 : 0);
    const int rowbase = bi * 128;

    const int wy  = wid & 1,  wx = wid >> 1;
    const int m0w = wy * 64,  n0w = wx * 32;

    const int bj0 = (bi + d0) % NTILES;
    prefetch_tile(g_h, rowbase, OFF_A, sb, tid);
    prefetch_tile(g_h, bj0 * 128, OFF_B(0), sb, tid);
    stage_sq(sb, 0, bj0, tid);
    CP_COMMIT();

    unsigned int* colmin = reinterpret_cast<unsigned int*>(smem + OFF_COLMIN);
    if (tid < 128) colmin[tid] = 0x7f800000u;

    __half2 sqi2[4][2];
    float   rmin[4][2];
    #pragma unroll
    for (int mt = 0; mt < 4; mt++)
        #pragma unroll
        for (int h = 0; h < 2; h++) {
            int r = m0w + mt * 16 + (lane >> 2) + h * 8;
            sqi2[mt][h] = __float2half2_rn(g_sq[rowbase + r]);
            rmin[mt][h] = __int_as_float(0x7f800000);
        }

    const int a_rbit = (lane >> 3) & 1;
    const int a_cbit = (lane >> 4) & 1;
    const int b_rbit = (lane >> 4) & 1;
    const int b_cbit = (lane >> 3) & 1;
    const int l7 = lane & 7;
    const __half2 NEG2 = __float2half2_rn(-2.0f);
    const __half2 HINF2 = __half2half2(__ushort_as_half(0x7C00));

    for (int t = 0; t < ntl; t++) {
        const int b  = t & 1, nb = b ^ 1;
        const int jt = (bi + d0 + t) % NTILES;

        if (t + 1 < ntl) {
            const int jn = (bi + d0 + t + 1) % NTILES;
            prefetch_tile(g_h, jn * 128, OFF_B(nb), sb, tid);
            stage_sq(sb, nb, jn, tid);
            CP_COMMIT();
            CP_WAIT(1);
        } else {
            CP_WAIT(0);
        }
        __syncthreads();

        uint32_t acc[4][4][2];
        #pragma unroll
        for (int mt = 0; mt < 4; mt++)
            #pragma unroll
            for (int nt = 0; nt < 4; nt++) { acc[mt][nt][0] = 0u; acc[mt][nt][1] = 0u; }

        const uint32_t Ab = sb + OFF_A, Bb = sb + OFF_B(b);

        #pragma unroll
        for (int ks = 0; ks < 8; ks++) {
            const int c0 = ks * 2;
            uint32_t af[4][4], bf[2][4];
            #pragma unroll
            for (int mt = 0; mt < 4; mt++) {
                int row = m0w + mt * 16 + l7 + a_rbit * 8;
                ldsm4(af[mt], Ab + ((uint32_t)row << 8) +
                              ((uint32_t)((c0 + a_cbit) ^ (row & 7)) << 4));
            }
            #pragma unroll
            for (int bt = 0; bt < 2; bt++) {
                int row = n0w + bt * 16 + l7 + b_rbit * 8;
                ldsm4(bf[bt], Bb + ((uint32_t)row << 8) +
                              ((uint32_t)((c0 + b_cbit) ^ (row & 7)) << 4));
            }
            #pragma unroll
            for (int mt = 0; mt < 4; mt++)
                #pragma unroll
                for (int nt = 0; nt < 4; nt++)
                    mma16816h(acc[mt][nt], af[mt],
                              bf[nt >> 1][(nt & 1) * 2],
                              bf[nt >> 1][(nt & 1) * 2 + 1]);
        }

        if ((bi & 31) == (jt & 31)) {
            #pragma unroll
            for (int mt = 0; mt < 4; mt++) {
                const int r0 = m0w + mt * 16 + (lane >> 2);
                const int r1 = r0 + 8;
                #pragma unroll
                for (int nt = 0; nt < 4; nt++) {
                    const int c0i = n0w + nt * 8 + (lane & 3) * 2;
                    if (r0 == c0i)     acc[mt][nt][0] = (acc[mt][nt][0] & 0xFFFF0000u) | 0x0000FC00u;
                    if (r0 == c0i + 1) acc[mt][nt][0] = (acc[mt][nt][0] & 0x0000FFFFu) | 0xFC000000u;
                    if (r1 == c0i)     acc[mt][nt][1] = (acc[mt][nt][1] & 0xFFFF0000u) | 0x0000FC00u;
                    if (r1 == c0i + 1) acc[mt][nt][1] = (acc[mt][nt][1] & 0x0000FFFFu) | 0xFC000000u;
                }
            }
        }

        const __half2* sqjh = reinterpret_cast<const __half2*>(smem + OFF_SQJH(b));
        __half2 rh2[4][2], ch2[4];
        #pragma unroll
        for (int mt = 0; mt < 4; mt++) { rh2[mt][0] = HINF2; rh2[mt][1] = HINF2; }
        #pragma unroll
        for (int nt = 0; nt < 4; nt++) ch2[nt] = HINF2;

        #pragma unroll
        for (int nt = 0; nt < 4; nt++) {
            __half2 sj2 = sqjh[(n0w + nt * 8) / 2 + (lane & 3)];
            #pragma unroll
            for (int mt = 0; mt < 4; mt++) {
                __half2 a0 = *reinterpret_cast<__half2*>(&acc[mt][nt][0]);
                __half2 a1 = *reinterpret_cast<__half2*>(&acc[mt][nt][1]);
                rh2[mt][0] = __hmin2(rh2[mt][0], __hfma2(a0, NEG2, sj2));
                rh2[mt][1] = __hmin2(rh2[mt][1], __hfma2(a1, NEG2, sj2));
                ch2[nt] = __hmin2(ch2[nt], __hfma2(a0, NEG2, sqi2[mt][0]));
                ch2[nt] = __hmin2(ch2[nt], __hfma2(a1, NEG2, sqi2[mt][1]));
            }
        }

        #pragma unroll
        for (int mt = 0; mt < 4; mt++)
            #pragma unroll
            for (int h = 0; h < 2; h++) {
                float2 f = __half22float2(rh2[mt][h]);
                rmin[mt][h] = fminf(rmin[mt][h], fminf(f.x, f.y));
            }

        #pragma unroll
        for (int nt = 0; nt < 4; nt++) {
            ch2[nt] = shfl_hmin2(ch2[nt], 4);
            ch2[nt] = shfl_hmin2(ch2[nt], 8);
            ch2[nt] = shfl_hmin2(ch2[nt], 16);
        }
        if (lane < 4) {
            const float* sqjf = reinterpret_cast<const float*>(smem + OFF_SQJ(b));
            #pragma unroll
            for (int nt = 0; nt < 4; nt++) {
                int c = n0w + nt * 8 + lane * 2;
                float2 f = __half22float2(ch2[nt]);
                float v0 = fmaxf(f.x + sqjf[c], 0.f);
                float v1 = fmaxf(f.y + sqjf[c + 1], 0.f);
                atomicMin(&colmin[c],     __float_as_uint(v0));
                atomicMin(&colmin[c + 1], __float_as_uint(v1));
            }
        }
        __syncthreads();

        if (tid < 128) {
            atomicMin(&g_rowmin[jt * 128 + tid], colmin[tid]);
            colmin[tid] = 0x7f800000u;
        }
    }

    #pragma unroll
    for (int mt = 0; mt < 4; mt++)
        #pragma unroll
        for (int h = 0; h < 2; h++) {
            float v = rmin[mt][h];
            v = fminf(v, __shfl_xor_sync(0xffffffffu, v, 1));
            v = fminf(v, __shfl_xor_sync(0xffffffffu, v, 2));
            if ((lane & 3) == 0) {
                int r = m0w + mt * 16 + (lane >> 2) + h * 8;
                float d2 = fmaxf(v + g_sq[rowbase + r], 0.f);
                atomicMin(&g_rowmin[rowbase + r], __float_as_uint(d2));
            }
        }

    // ================= phase 3: last CTA reduces and writes out ==============
    __syncthreads();
    __shared__ int s_last;
    if (tid == 0) {
        __threadfence();
        unsigned int old = atomicAdd(&g_bar2, 1u);
        s_last = (old == (unsigned)(GRID - 1)) ? 1 : 0;
    }
    __syncthreads();
    if (s_last) {
        __threadfence();
        __shared__ float sl[TPB];
        __shared__ float sr[TPB];
        float ls = 0.0f, rs = 0.0f;
        for (int i = tid; i < NTOT; i += TPB) {
            float pm = g_posmax[i];
            float nm = __uint_as_float(g_rowmin[i]);
            float pd = (pm > 0.0f) ? sqrtf(pm) : 0.0f;
            float nd = (nm > 0.0f) ? sqrtf(nm) : 0.0f;
            ls += fmaxf(pd - nd + MARGIN, 0.0f);
            rs += g_regpart[i];
        }
        sl[tid] = ls; sr[tid] = rs;
        __syncthreads();
        #pragma unroll
        for (int s = TPB / 2; s; s >>= 1) {
            if (tid < s) { sl[tid] += sl[tid + s]; sr[tid] += sr[tid + s]; }
            __syncthreads();
        }
        if (tid == 0) {
            out[0] = sl[0] / (float)NTOT + ALPHA * (sr[0] / (float)(NTOT * DIM));
            g_bar1 = 0;   // reset for next graph replay
            g_bar2 = 0;
            __threadfence();
        }
    }
}

// ---------------------------------------------------------------------------
extern "C" void kernel_launch(void* const* d_in, const int* in_sizes, int n_in,
                              void* d_out, int out_size) {
    const float* a = (const float*)d_in[0];
    const float* p = (const float*)d_in[1];
    const float* n = (const float*)d_in[2];
    float* out = (float*)d_out;

    cudaFuncSetAttribute(fused_kernel,
                         cudaFuncAttributeMaxDynamicSharedMemorySize, SMEM_TOTAL);

    fused_kernel<<<GRID, TPB, SMEM_TOTAL>>>(a, p, n, out);
}

// round 11
// speedup vs baseline: 2.2381x; 1.1916x over previous
#include <cuda_runtime.h>
#include <cuda_fp16.h>
#include <cstdint>
#include <math.h>

// Inputs: a [4096,128] f32, p [4096,128] f32, n [4096,128] f32. Output: 1 f32.

#define B_SIZE 4096
#define DIM    128
#define NTOT   12288
#define NTILES 96
#define TPB    512
#define MARGIN 0.4f
#define ALPHA  0.01f

// ---- smem layout (bytes) ----
#define OFF_SQJ(b)  ((b) * 512)          // fp32 sqj, per buffer
#define OFF_COLMIN  1024
#define OFF_SQJH(b) (1536 + (b) * 256)   // fp16 sqj, per buffer
#define OFF_A       2048
#define OFF_B(b)    (OFF_A + 32768 + (b) * 32768)
#define SMEM_TOTAL  (OFF_A + 32768 + 2 * 32768)   // 100352

// ---- device scratch ----
__device__ float         g_sq[NTOT];
__device__ __half        g_sqh[NTOT];
__device__ unsigned int  g_rowmin[NTOT];
__device__ float         g_posmax[NTOT];
__device__ float         g_regpart[NTOT];
__device__ __half        g_h[NTOT * DIM];

// ---- helpers ----
__device__ __forceinline__ uint32_t smem_u32(const void* p) {
    uint32_t a;
    asm("{ .reg .u64 t; cvta.to.shared.u64 t, %1; cvt.u32.u64 %0, t; }"
        : "=r"(a) : "l"(p));
    return a;
}
__device__ __forceinline__ void cp16(uint32_t dst, const void* src) {
    asm volatile("cp.async.cg.shared.global [%0], [%1], 16;"
                 :: "r"(dst), "l"(src));
}
#define CP_COMMIT() asm volatile("cp.async.commit_group;" ::: "memory")
#define CP_WAIT(n)  asm volatile("cp.async.wait_group %0;" :: "n"(n) : "memory")

__device__ __forceinline__ void ldsm4(uint32_t* r, uint32_t addr) {
    asm volatile("ldmatrix.sync.aligned.m8n8.x4.shared.b16 {%0,%1,%2,%3}, [%4];"
                 : "=r"(r[0]), "=r"(r[1]), "=r"(r[2]), "=r"(r[3]) : "r"(addr));
}
__device__ __forceinline__ void mma16816h(uint32_t* d, const uint32_t* a,
                                          uint32_t b0, uint32_t b1) {
    asm volatile("mma.sync.aligned.m16n8k16.row.col.f16.f16.f16.f16 "
                 "{%0,%1}, {%2,%3,%4,%5}, {%6,%7}, {%0,%1};"
                 : "+r"(d[0]), "+r"(d[1])
                 : "r"(a[0]), "r"(a[1]), "r"(a[2]), "r"(a[3]),
                   "r"(b0), "r"(b1));
}
__device__ __forceinline__ __half2 shfl_hmin2(__half2 v, int ofs) {
    uint32_t u = __shfl_xor_sync(0xffffffffu,
                                 *reinterpret_cast<uint32_t*>(&v), ofs);
    return __hmin2(v, *reinterpret_cast<__half2*>(&u));
}

// ---------------------------------------------------------------------------
// prep: one warp per column c; loads a_c/p_c/n_c once, emits everything.
// ---------------------------------------------------------------------------
__global__ void __launch_bounds__(256) prep_kernel(const float* __restrict__ a,
                                                   const float* __restrict__ p,
                                                   const float* __restrict__ n) {
    int c    = (blockIdx.x * 256 + threadIdx.x) >> 5;   // 0..4095
    int lane = threadIdx.x & 31;

    float4 xa = reinterpret_cast<const float4*>(a + (size_t)c * DIM)[lane];
    float4 xp = reinterpret_cast<const float4*>(p + (size_t)c * DIM)[lane];
    float4 xn = reinterpret_cast<const float4*>(n + (size_t)c * DIM)[lane];

    float as[4] = {xa.x, xa.y, xa.z, xa.w};
    float ps[4] = {xp.x, xp.y, xp.z, xp.w};
    float ns[4] = {xn.x, xn.y, xn.z, xn.w};

    float sqa = 0.f, sqp = 0.f, sqn = 0.f;
    float ra = 0.f, rp = 0.f, rn = 0.f;
    float eap = 0.f, ean = 0.f, epn = 0.f;
    #pragma unroll
    for (int i = 0; i < 4; i++) {
        sqa += as[i] * as[i];  sqp += ps[i] * ps[i];  sqn += ns[i] * ns[i];
        float ta = fabsf(as[i]) - 1.f; ra += ta * ta;
        float tp = fabsf(ps[i]) - 1.f; rp += tp * tp;
        float tn = fabsf(ns[i]) - 1.f; rn += tn * tn;
        float d1 = as[i] - ps[i]; eap += d1 * d1;
        float d2 = as[i] - ns[i]; ean += d2 * d2;
        float d3 = ps[i] - ns[i]; epn += d3 * d3;
    }
    #pragma unroll
    for (int ofs = 16; ofs; ofs >>= 1) {
        sqa += __shfl_xor_sync(0xffffffffu, sqa, ofs);
        sqp += __shfl_xor_sync(0xffffffffu, sqp, ofs);
        sqn += __shfl_xor_sync(0xffffffffu, sqn, ofs);
        ra  += __shfl_xor_sync(0xffffffffu, ra,  ofs);
        rp  += __shfl_xor_sync(0xffffffffu, rp,  ofs);
        rn  += __shfl_xor_sync(0xffffffffu, rn,  ofs);
        eap += __shfl_xor_sync(0xffffffffu, eap, ofs);
        ean += __shfl_xor_sync(0xffffffffu, ean, ofs);
        epn += __shfl_xor_sync(0xffffffffu, epn, ofs);
    }
    if (lane == 0) {
        g_sq[c]              = sqa;
        g_sq[c + B_SIZE]     = sqp;
        g_sq[c + 2 * B_SIZE] = sqn;
        g_sqh[c]              = __float2half_rn(sqa);
        g_sqh[c + B_SIZE]     = __float2half_rn(sqp);
        g_sqh[c + 2 * B_SIZE] = __float2half_rn(sqn);
        g_regpart[c]              = ra;
        g_regpart[c + B_SIZE]     = rp;
        g_regpart[c + 2 * B_SIZE] = rn;
        g_posmax[c]               = fmaxf(eap, ean);
        g_posmax[c + B_SIZE]      = fmaxf(eap, epn);
        g_posmax[c + 2 * B_SIZE]  = fmaxf(ean, epn);
        g_rowmin[c]               = 0x7f800000u;
        g_rowmin[c + B_SIZE]      = 0x7f800000u;
        g_rowmin[c + 2 * B_SIZE]  = 0x7f800000u;
    }

    #pragma unroll
    for (int seg = 0; seg < 3; seg++) {
        const float* s = (seg == 0) ? as : (seg == 1) ? ps : ns;
        unsigned h0 = 0, h1 = 0;
        #pragma unroll
        for (int i = 0; i < 4; i++) {
            unsigned hb = __half_as_ushort(__float2half_rn(s[i]));
            if (i < 2) h0 |= hb << (16 * i);
            else       h1 |= hb << (16 * (i - 2));
        }
        reinterpret_cast<uint2*>(g_h)[(c + seg * B_SIZE) * 32 + lane] =
            make_uint2(h0, h1);
    }
}

// ---------------------------------------------------------------------------
__device__ __forceinline__ void prefetch_tile(const __half* __restrict__ g,
                                              int rowbase, uint32_t sm_off,
                                              uint32_t sb, int tid) {
    const uint4* src = reinterpret_cast<const uint4*>(g) + (size_t)rowbase * 16;
    #pragma unroll
    for (int i = 0; i < 4; i++) {
        int ch = tid + i * 512;
        int m = ch >> 4, c = ch & 15;
        uint32_t dst = sb + sm_off + ((uint32_t)m << 8) + ((uint32_t)(c ^ (m & 7)) << 4);
        cp16(dst, src + ch);
    }
}
__device__ __forceinline__ void stage_sq(uint32_t sb, int buf, int jt, int tid) {
    if (tid < 32) cp16(sb + OFF_SQJ(buf) + tid * 16, g_sq + jt * 128 + tid * 4);
    else if (tid < 48)
        cp16(sb + OFF_SQJH(buf) + (tid - 32) * 16, g_sqh + jt * 128 + (tid - 32) * 8);
}

// ---------------------------------------------------------------------------
// tile kernel: symmetric cyclic coverage, 512 threads, warp tile 32x32.
// ---------------------------------------------------------------------------
__global__ void __launch_bounds__(TPB, 2) tile_kernel() {
    extern __shared__ char smem[];
    uint32_t sb = smem_u32(smem);
    const int tid  = threadIdx.x;
    const int wid  = tid >> 5;
    const int lane = tid & 31;

    const int bi   = blockIdx.x / 3;
    const int grp  = blockIdx.x % 3;
    const int d0   = grp * 16;
    const int ntl  = 16 + ((grp == 2 && bi < 48) ? 1 : 0);
    const int rowbase = bi * 128;

    // warp layout: 4 warps in M (32 rows) x 4 warps in N (32 cols)
    const int m0w = (wid & 3) * 32;
    const int n0w = (wid >> 2) * 32;

    const int bj0 = (bi + d0) % NTILES;
    prefetch_tile(g_h, rowbase, OFF_A, sb, tid);
    prefetch_tile(g_h, bj0 * 128, OFF_B(0), sb, tid);
    stage_sq(sb, 0, bj0, tid);
    CP_COMMIT();

    unsigned int* colmin = reinterpret_cast<unsigned int*>(smem + OFF_COLMIN);
    if (tid < 128) colmin[tid] = 0x7f800000u;

    __half2 sqi2[2][2];
    float   rmin[2][2];
    #pragma unroll
    for (int mt = 0; mt < 2; mt++)
        #pragma unroll
        for (int h = 0; h < 2; h++) {
            int r = m0w + mt * 16 + (lane >> 2) + h * 8;
            sqi2[mt][h] = __float2half2_rn(g_sq[rowbase + r]);
            rmin[mt][h] = __int_as_float(0x7f800000);
        }

    const int a_rbit = (lane >> 3) & 1;
    const int a_cbit = (lane >> 4) & 1;
    const int b_rbit = (lane >> 4) & 1;
    const int b_cbit = (lane >> 3) & 1;
    const int l7 = lane & 7;
    const __half2 NEG2 = __float2half2_rn(-2.0f);
    const __half2 HINF2 = __half2half2(__ushort_as_half(0x7C00));

    for (int t = 0; t < ntl; t++) {
        const int b  = t & 1, nb = b ^ 1;
        const int jt = (bi + d0 + t) % NTILES;

        if (t + 1 < ntl) {
            const int jn = (bi + d0 + t + 1) % NTILES;
            prefetch_tile(g_h, jn * 128, OFF_B(nb), sb, tid);
            stage_sq(sb, nb, jn, tid);
            CP_COMMIT();
            CP_WAIT(1);
        } else {
            CP_WAIT(0);
        }
        __syncthreads();

        // ---- MMA: fp16, K=128, warp tile 32x32 ----
        uint32_t acc[2][4][2];
        #pragma unroll
        for (int mt = 0; mt < 2; mt++)
            #pragma unroll
            for (int nt = 0; nt < 4; nt++) { acc[mt][nt][0] = 0u; acc[mt][nt][1] = 0u; }

        const uint32_t Ab = sb + OFF_A, Bb = sb + OFF_B(b);

        #pragma unroll
        for (int ks = 0; ks < 8; ks++) {
            const int c0 = ks * 2;
            uint32_t af[2][4], bf[2][4];
            #pragma unroll
            for (int mt = 0; mt < 2; mt++) {
                int row = m0w + mt * 16 + l7 + a_rbit * 8;
                ldsm4(af[mt], Ab + ((uint32_t)row << 8) +
                              ((uint32_t)((c0 + a_cbit) ^ (row & 7)) << 4));
            }
            #pragma unroll
            for (int bt = 0; bt < 2; bt++) {
                int row = n0w + bt * 16 + l7 + b_rbit * 8;
                ldsm4(bf[bt], Bb + ((uint32_t)row << 8) +
                              ((uint32_t)((c0 + b_cbit) ^ (row & 7)) << 4));
            }
            #pragma unroll
            for (int mt = 0; mt < 2; mt++)
                #pragma unroll
                for (int nt = 0; nt < 4; nt++)
                    mma16816h(acc[mt][nt], af[mt],
                              bf[nt >> 1][(nt & 1) * 2],
                              bf[nt >> 1][(nt & 1) * 2 + 1]);
        }

        // ---- diag mask: splat -inf into dot at same-label positions ----
        if ((bi & 31) == (jt & 31)) {
            #pragma unroll
            for (int mt = 0; mt < 2; mt++) {
                const int r0 = m0w + mt * 16 + (lane >> 2);
                const int r1 = r0 + 8;
                #pragma unroll
                for (int nt = 0; nt < 4; nt++) {
                    const int c0i = n0w + nt * 8 + (lane & 3) * 2;
                    if (r0 == c0i)     acc[mt][nt][0] = (acc[mt][nt][0] & 0xFFFF0000u) | 0x0000FC00u;
                    if (r0 == c0i + 1) acc[mt][nt][0] = (acc[mt][nt][0] & 0x0000FFFFu) | 0xFC000000u;
                    if (r1 == c0i)     acc[mt][nt][1] = (acc[mt][nt][1] & 0xFFFF0000u) | 0x0000FC00u;
                    if (r1 == c0i + 1) acc[mt][nt][1] = (acc[mt][nt][1] & 0x0000FFFFu) | 0xFC000000u;
                }
            }
        }

        // ---- packed epilogue ----
        const __half2* sqjh = reinterpret_cast<const __half2*>(smem + OFF_SQJH(b));
        __half2 rh2[2][2], ch2[4];
        #pragma unroll
        for (int mt = 0; mt < 2; mt++) { rh2[mt][0] = HINF2; rh2[mt][1] = HINF2; }
        #pragma unroll
        for (int nt = 0; nt < 4; nt++) ch2[nt] = HINF2;

        #pragma unroll
        for (int nt = 0; nt < 4; nt++) {
            __half2 sj2 = sqjh[(n0w + nt * 8) / 2 + (lane & 3)];
            #pragma unroll
            for (int mt = 0; mt < 2; mt++) {
                __half2 a0 = *reinterpret_cast<__half2*>(&acc[mt][nt][0]);
                __half2 a1 = *reinterpret_cast<__half2*>(&acc[mt][nt][1]);
                rh2[mt][0] = __hmin2(rh2[mt][0], __hfma2(a0, NEG2, sj2));
                rh2[mt][1] = __hmin2(rh2[mt][1], __hfma2(a1, NEG2, sj2));
                ch2[nt] = __hmin2(ch2[nt], __hfma2(a0, NEG2, sqi2[mt][0]));
                ch2[nt] = __hmin2(ch2[nt], __hfma2(a1, NEG2, sqi2[mt][1]));
            }
        }

        #pragma unroll
        for (int mt = 0; mt < 2; mt++)
            #pragma unroll
            for (int h = 0; h < 2; h++) {
                float2 f = __half22float2(rh2[mt][h]);
                rmin[mt][h] = fminf(rmin[mt][h], fminf(f.x, f.y));
            }

        #pragma unroll
        for (int nt = 0; nt < 4; nt++) {
            ch2[nt] = shfl_hmin2(ch2[nt], 4);
            ch2[nt] = shfl_hmin2(ch2[nt], 8);
            ch2[nt] = shfl_hmin2(ch2[nt], 16);
        }
        if (lane < 4) {
            const float* sqjf = reinterpret_cast<const float*>(smem + OFF_SQJ(b));
            #pragma unroll
            for (int nt = 0; nt < 4; nt++) {
                int c = n0w + nt * 8 + lane * 2;
                float2 f = __half22float2(ch2[nt]);
                float v0 = fmaxf(f.x + sqjf[c], 0.f);
                float v1 = fmaxf(f.y + sqjf[c + 1], 0.f);
                atomicMin(&colmin[c],     __float_as_uint(v0));
                atomicMin(&colmin[c + 1], __float_as_uint(v1));
            }
        }
        __syncthreads();

        if (tid < 128) {
            atomicMin(&g_rowmin[jt * 128 + tid], colmin[tid]);
            colmin[tid] = 0x7f800000u;
        }
    }

    // ---- final row-min: add sqi (fp32), reduce column-lanes, atomic ----
    #pragma unroll
    for (int mt = 0; mt < 2; mt++)
        #pragma unroll
        for (int h = 0; h < 2; h++) {
            float v = rmin[mt][h];
            v = fminf(v, __shfl_xor_sync(0xffffffffu, v, 1));
            v = fminf(v, __shfl_xor_sync(0xffffffffu, v, 2));
            if ((lane & 3) == 0) {
                int r = m0w + mt * 16 + (lane >> 2) + h * 8;
                float d2 = fmaxf(v + g_sq[rowbase + r], 0.f);
                atomicMin(&g_rowmin[rowbase + r], __float_as_uint(d2));
            }
        }
}

// ---------------------------------------------------------------------------
__global__ void finalize_kernel(float* __restrict__ out) {
    __shared__ float sl[1024];
    __shared__ float sr[1024];
    int t = threadIdx.x;
    float ls = 0.0f, rs = 0.0f;
    for (int i = t; i < NTOT; i += 1024) {
        float pm = g_posmax[i];
        float nm = __uint_as_float(g_rowmin[i]);
        float pd = (pm > 0.0f) ? sqrtf(pm) : 0.0f;
        float nd = (nm > 0.0f) ? sqrtf(nm) : 0.0f;
        ls += fmaxf(pd - nd + MARGIN, 0.0f);
        rs += g_regpart[i];
    }
    sl[t] = ls; sr[t] = rs;
    __syncthreads();
    #pragma unroll
    for (int s = 512; s; s >>= 1) {
        if (t < s) { sl[t] += sl[t + s]; sr[t] += sr[t + s]; }
        __syncthreads();
    }
    if (t == 0)
        out[0] = sl[0] / (float)NTOT + ALPHA * (sr[0] / (float)(NTOT * DIM));
}

// ---------------------------------------------------------------------------
extern "C" void kernel_launch(void* const* d_in, const int* in_sizes, int n_in,
                              void* d_out, int out_size) {
    const float* a = (const float*)d_in[0];
    const float* p = (const float*)d_in[1];
    const float* n = (const float*)d_in[2];
    float* out = (float*)d_out;

    cudaFuncSetAttribute(tile_kernel,
                         cudaFuncAttributeMaxDynamicSharedMemorySize, SMEM_TOTAL);

    prep_kernel<<<B_SIZE / 8, 256>>>(a, p, n);
    tile_kernel<<<NTILES * 3, TPB, SMEM_TOTAL>>>();
    finalize_kernel<<<1, 1024>>>(out);
}